// round 14
// baseline (speedup 1.0000x reference)
#include <cuda_runtime.h>
#include <cstdint>

// FPS + gather, bit-exact vs JAX/XLA (distance = fma(dz,dz, fma(dx,dx, rn(dy*dy)))).
// B=8, N=131072, S=4096.
//
// R13 = R12 (packed f32x2 compute, volatile tagged slots, self-detect, coord
// prefetch) with ALL argmax reduces switched from u64 shuffle chains (5+4+4
// dependent SHFL levels, ~450-500cyc) to exact redux.sync pairs:
//   vmax = redux.max(value_bits); imin = redux.min(tie ? idx : INF)
// (~80cyc/level). Slot: value[61:30] | idx[29:13] | tag[12:0].

#define NB 8
#define NP 131072
#define NS 4096
#define CPB 16                 // CTAs per batch
#define NT 512                 // threads per CTA
#define ROUNDS (NS - 1)
#define PPC (NP / CPB)         // 8192 points per CTA

#define ADD2(r, a, b) asm("add.rn.f32x2 %0, %1, %2;" : "=l"(r) : "l"(a), "l"(b))
#define MUL2(r, a, b) asm("mul.rn.f32x2 %0, %1, %2;" : "=l"(r) : "l"(a), "l"(b))
#define FMA2(r, a, b, c) asm("fma.rn.f32x2 %0, %1, %2, %3;" : "=l"(r) : "l"(a), "l"(b), "l"(c))
#define PACK2(r, lo, hi) asm("mov.b64 %0, {%1, %2};" : "=l"(r) : "f"(lo), "f"(hi))
#define UNPACK2(lo, hi, r) asm("mov.b64 {%0, %1}, %2;" : "=f"(lo), "=f"(hi) : "l"(r))

__device__ float4 g_xyz[NB * NP];
struct __align__(2048) BSlots { unsigned long long key[CPB]; };
__device__ BSlots g_slots[NB];

__global__ void fps_prep_kernel(const float* __restrict__ pts) {
    if (blockIdx.x == 0 && threadIdx.x < NB * CPB) {
        g_slots[threadIdx.x / CPB].key[threadIdx.x % CPB] = 0ull;  // tag 0 < 1
    }
    int i = blockIdx.x * blockDim.x + threadIdx.x;
    int stride = gridDim.x * blockDim.x;
    for (; i < NB * NP; i += stride) {
        g_xyz[i] = make_float4(pts[3 * i + 0], pts[3 * i + 1], pts[3 * i + 2], 0.0f);
    }
}

__global__ void __launch_bounds__(NT, 1) fps_main_kernel(float* __restrict__ out) {
    const int b    = blockIdx.x / CPB;
    const int c    = blockIdx.x % CPB;
    const int tid  = threadIdx.x;
    const int lane = tid & 31;
    const int wid  = tid >> 5;
    const int base = c * PPC;
    const float4* __restrict__ P = g_xyz + b * NP;
    unsigned long long* __restrict__ slots = g_slots[b].key;

    // one-time: 16 points/thread -> 8 packed pairs per coordinate
    unsigned long long px2[8], py2[8], pz2[8];
    float md[16];
#pragma unroll
    for (int j = 0; j < 4; ++j) {
        const int e = j * NT + tid;
#pragma unroll
        for (int h = 0; h < 2; ++h) {
            float4 q0 = P[base + e * 4 + h * 2 + 0];
            float4 q1 = P[base + e * 4 + h * 2 + 1];
            PACK2(px2[j * 2 + h], q0.x, q1.x);
            PACK2(py2[j * 2 + h], q0.y, q1.y);
            PACK2(pz2[j * 2 + h], q0.z, q1.z);
        }
    }
#pragma unroll
    for (int i = 0; i < 16; ++i) md[i] = 1e10f;   // BIG

    __shared__ unsigned s_v[NT / 32];
    __shared__ unsigned s_i[NT / 32];
    __shared__ float s_win[3];

    // selection 0 is always index 0
    float4 p0 = P[0];
    float lx = p0.x, ly = p0.y, lz = p0.z;
    if (c == 0 && tid == 0) {
        out[(b * NS + 0) * 3 + 0] = lx;
        out[(b * NS + 0) * 3 + 1] = ly;
        out[(b * NS + 0) * 3 + 2] = lz;
    }

    const int tb = base + tid * 4;

    for (int r = 0; r < ROUNDS; ++r) {
        float bestv = -1.0f;
        int   besti = 0;

        // packed negated last point (exact: a-b == a+(-b))
        unsigned long long nlx2, nly2, nlz2;
        { float nx = -lx, ny = -ly, nz = -lz;
          PACK2(nlx2, nx, nx); PACK2(nly2, ny, ny); PACK2(nlz2, nz, nz); }

#pragma unroll
        for (int p = 0; p < 8; ++p) {
            const int j = p >> 1, h = p & 1;
            const int idx0 = tb + j * (NT * 4) + h * 2;
            unsigned long long dx2, dy2, dz2, s2;
            // per-lane FROZEN sequence: dx=sub; dy=sub; dz=sub;
            // d = fma(dz,dz, fma(dx,dx, mul(dy,dy)))
            ADD2(dx2, px2[p], nlx2);
            ADD2(dy2, py2[p], nly2);
            ADD2(dz2, pz2[p], nlz2);
            MUL2(s2, dy2, dy2);
            FMA2(s2, dx2, dx2, s2);
            FMA2(s2, dz2, dz2, s2);
            float d0, d1;
            UNPACK2(d0, d1, s2);
            float m0 = fminf(md[p * 2 + 0], d0);
            md[p * 2 + 0] = m0;
            if (m0 > bestv) { bestv = m0; besti = idx0; }
            float m1 = fminf(md[p * 2 + 1], d1);
            md[p * 2 + 1] = m1;
            if (m1 > bestv) { bestv = m1; besti = idx0 + 1; }
        }

        // warp argmax: redux pair (exact first-occurrence semantics)
        unsigned vbits = __float_as_uint(bestv);          // v >= 0 -> monotonic bits
        unsigned vmaxw = __reduce_max_sync(0xffffffffu, vbits);
        unsigned candw = (vbits == vmaxw) ? (unsigned)besti : 0xFFFFFFFFu;
        unsigned iminw = __reduce_min_sync(0xffffffffu, candw);
        if (lane == 0) { s_v[wid] = vmaxw; s_i[wid] = iminw; }
        __syncthreads();

        if (wid == 0) {
            const unsigned long long tag = (unsigned long long)(r + 1);  // 13 bits

            // CTA argmax over 16 warp records: redux pair (all lanes get result)
            unsigned vb = (lane < 16) ? s_v[lane] : 0u;
            unsigned ib = (lane < 16) ? s_i[lane] : 0xFFFFFFFFu;
            unsigned vmaxc = __reduce_max_sync(0xffffffffu, vb);
            unsigned candc = (vb == vmaxc) ? ib : 0xFFFFFFFFu;
            unsigned iminc = __reduce_min_sync(0xffffffffu, candc);

            unsigned long long myslot =
                ((unsigned long long)vmaxc << 30) |
                ((unsigned long long)(iminc & 0x1FFFFu) << 13) | tag;
            if (lane == 0) {
                asm volatile("st.volatile.global.b64 [%0], %1;"
                             :: "l"(&slots[c]), "l"(myslot) : "memory");
            }

            // single-hop: poll 16 slots (one lane each); own slot self-detects;
            // prefetch candidate coords at detect time
            unsigned long long k = 0ull;
            float4 w4 = make_float4(0.f, 0.f, 0.f, 0.f);
            bool got = (lane >= CPB);
            if (lane == c) {
                k = myslot;
                got = true;
                w4 = P[iminc];                       // own slice: L1 hit
            }
            do {
                if (!got) {
                    asm volatile("ld.volatile.global.b64 %0, [%1];"
                                 : "=l"(k) : "l"(&slots[lane]) : "memory");
                    if ((k & 0x1FFFull) == tag) {
                        got = true;
                        w4 = P[(int)((k >> 13) & 0x1FFFFull)];   // overlap
                    }
                }
            } while (!__all_sync(0xffffffffu, got));

            // cross-CTA argmax: redux pair; winner lane unique (disjoint idx)
            unsigned pv  = (lane < CPB) ? (unsigned)(k >> 30) : 0u;
            unsigned pix = (lane < CPB) ? (unsigned)((k >> 13) & 0x1FFFFull)
                                        : 0xFFFFFFFFu;
            unsigned gv = __reduce_max_sync(0xffffffffu, pv);
            unsigned gc = (lane < CPB && pv == gv) ? pix : 0xFFFFFFFFu;
            unsigned gi = __reduce_min_sync(0xffffffffu, gc);
            unsigned wl = __ffs(__ballot_sync(0xffffffffu, gc == gi)) - 1u;
            float wx = __shfl_sync(0xffffffffu, w4.x, wl);
            float wy = __shfl_sync(0xffffffffu, w4.y, wl);
            float wz = __shfl_sync(0xffffffffu, w4.z, wl);
            if (lane == 0) {
                s_win[0] = wx; s_win[1] = wy; s_win[2] = wz;
                if (c == 0) {
                    out[(b * NS + r + 1) * 3 + 0] = wx;
                    out[(b * NS + r + 1) * 3 + 1] = wy;
                    out[(b * NS + r + 1) * 3 + 2] = wz;
                }
            }
        }
        __syncthreads();
        lx = s_win[0]; ly = s_win[1]; lz = s_win[2];
    }
}

extern "C" void kernel_launch(void* const* d_in, const int* in_sizes, int n_in,
                              void* d_out, int out_size) {
    const float* pts = (const float*)d_in[0];
    float* out = (float*)d_out;
    (void)in_sizes; (void)n_in; (void)out_size;

    fps_prep_kernel<<<512, 256>>>(pts);
    fps_main_kernel<<<NB * CPB, NT>>>(out);
}